// round 9
// baseline (speedup 1.0000x reference)
#include <cuda_runtime.h>
#include <cuda_bf16.h>
#include <math_constants.h>
#include <cstdint>

// Problem constants
#define SEQ     2048
#define NBATCH  4
#define FDIM    512
#define NQ      8192      // NBATCH * SEQ
#define NSTRIDE 1536      // q|k|v packed per token row
#define KNN     32

// GEMM tiling: CTA 128x128, KC=16, double-buffered cp.async (32KB static smem)
#define BM 128
#define BN 128
#define GKC 16            // K elems per staged chunk
#define GNCH 32           // 512 / 16
#define RSZ   4096        // one operand region: 128 rows x 16 bf16 x 2B
#define BUFB  16384       // 4 regions per buffer
// region offsets within a buffer
#define R_AHI 0
#define R_ALO 4096
#define R_BHI 8192
#define R_BLO 12288

// Scratch (no allocations allowed)
__device__ __align__(128) float          g_qkv[(size_t)NQ * NSTRIDE];  // ~50 MB
__device__ __align__(128) int            g_nn[NQ * KNN];               // 1 MB
__device__ __align__(128) __nv_bfloat16  g_xh[(size_t)NQ * FDIM];      // 8 MB
__device__ __align__(128) __nv_bfloat16  g_xl[(size_t)NQ * FDIM];      // 8 MB
__device__ __align__(128) __nv_bfloat16  g_wh[1536 * 512];             // 1.5 MB
__device__ __align__(128) __nv_bfloat16  g_wl[1536 * 512];             // 1.5 MB
__device__ __align__(128) float          g_mpart[4 * 16 * 8 * 32];     // 64 KB

// ---------------------------------------------------------------------------
__device__ __forceinline__ uint32_t smem_u32(const void* p) {
    uint32_t a;
    asm("{ .reg .u64 t; cvta.to.shared.u64 t, %1; cvt.u32.u64 %0, t; }" : "=r"(a) : "l"(p));
    return a;
}
// 32B-row swizzle: flip the 16B half for odd 128B blocks -> ldmatrix conflict-free
#define SW32(o) ((o) ^ ((((o) >> 7) & 1) << 4))

__device__ __forceinline__ void cpa16(uint32_t dst, const void* src) {
    asm volatile("cp.async.cg.shared.global [%0], [%1], 16;" :: "r"(dst), "l"(src));
}

// Split fp32 into hi/lo bf16 (x == hi + lo + O(2^-18 x))
__device__ __forceinline__ void split_bf16(float x, uint32_t& h, uint32_t& l) {
    __nv_bfloat16 bh = __float2bfloat16_rn(x);
    float r = x - __bfloat162float(bh);           // exact in fp32
    __nv_bfloat16 bl = __float2bfloat16_rn(r);
    h = (uint32_t)__bfloat16_as_ushort(bh);
    l = (uint32_t)__bfloat16_as_ushort(bl);
}
__device__ __forceinline__ void pack8(const float4& f0, const float4& f1,
                                      uint4& hi, uint4& lo) {
    uint32_t h0,l0,h1,l1,h2,l2,h3,l3,h4,l4,h5,l5,h6,l6,h7,l7;
    split_bf16(f0.x,h0,l0); split_bf16(f0.y,h1,l1);
    split_bf16(f0.z,h2,l2); split_bf16(f0.w,h3,l3);
    split_bf16(f1.x,h4,l4); split_bf16(f1.y,h5,l5);
    split_bf16(f1.z,h6,l6); split_bf16(f1.w,h7,l7);
    hi.x = h0 | (h1<<16); hi.y = h2 | (h3<<16); hi.z = h4 | (h5<<16); hi.w = h6 | (h7<<16);
    lo.x = l0 | (l1<<16); lo.y = l2 | (l3<<16); lo.z = l4 | (l5<<16); lo.w = l6 | (l7<<16);
}

__device__ __forceinline__ void ldsm_x4(uint32_t a, uint32_t& r0, uint32_t& r1,
                                        uint32_t& r2, uint32_t& r3) {
    asm volatile("ldmatrix.sync.aligned.m8n8.x4.shared.b16 {%0,%1,%2,%3}, [%4];"
                 : "=r"(r0), "=r"(r1), "=r"(r2), "=r"(r3) : "r"(a));
}
__device__ __forceinline__ void ldsm_x2(uint32_t a, uint32_t& r0, uint32_t& r1) {
    asm volatile("ldmatrix.sync.aligned.m8n8.x2.shared.b16 {%0,%1}, [%2];"
                 : "=r"(r0), "=r"(r1) : "r"(a));
}
__device__ __forceinline__ void mma_bf16(float* d, const uint32_t* a, const uint32_t* b) {
    asm volatile("mma.sync.aligned.m16n8k16.row.col.f32.bf16.bf16.f32 "
                 "{%0,%1,%2,%3}, {%4,%5,%6,%7}, {%8,%9}, {%0,%1,%2,%3};"
                 : "+f"(d[0]), "+f"(d[1]), "+f"(d[2]), "+f"(d[3])
                 : "r"(a[0]), "r"(a[1]), "r"(a[2]), "r"(a[3]), "r"(b[0]), "r"(b[1]));
}

// ---------------------------------------------------------------------------
// Pre-split x and W into bf16 hi/lo device copies (one pass, out of hot loop).
// One thread handles 8 contiguous elems. x: 524288 threads; W: 98304 threads.
// ---------------------------------------------------------------------------
#define XN8 (NQ * FDIM / 8)        // 524288
#define WN8 (1536 * 512 / 8)       // 98304
__global__ void __launch_bounds__(256)
split_kernel(const float* __restrict__ x,
             const float* __restrict__ Wq,
             const float* __restrict__ Wk,
             const float* __restrict__ Wv)
{
    const int idx = blockIdx.x * 256 + threadIdx.x;
    if (idx < XN8) {
        const size_t o = (size_t)idx * 8;
        float4 f0 = *(const float4*)(x + o);
        float4 f1 = *(const float4*)(x + o + 4);
        uint4 hi, lo; pack8(f0, f1, hi, lo);
        *(uint4*)(g_xh + o) = hi;
        *(uint4*)(g_xl + o) = lo;
    } else if (idx < XN8 + WN8) {
        const size_t o = (size_t)(idx - XN8) * 8;
        const int m = (int)(o >> 18);                 // 512*512 elems per matrix
        const size_t lo_idx = o & 262143;
        const float* src = (m == 0) ? Wq : (m == 1) ? Wk : Wv;
        float4 f0 = *(const float4*)(src + lo_idx);
        float4 f1 = *(const float4*)(src + lo_idx + 4);
        uint4 hi, lo; pack8(f0, f1, hi, lo);
        *(uint4*)(g_wh + o) = hi;
        *(uint4*)(g_wl + o) = lo;
    }
}

// ---------------------------------------------------------------------------
// QKV GEMM v3: C[m,n] = sum_k x[m,k]*W[n,k] via pre-split bf16 + mma.sync.
// cp.async double-buffered KC=16 pipeline, 32KB static smem, no conversion
// ALU in the loop. 8 warps in 2(M)x4(N), warp tile 64x32.
// ---------------------------------------------------------------------------
__global__ void __launch_bounds__(256, 1)
gemm_mma_kernel()
{
    __shared__ __align__(1024) char smem[2 * BUFB];
    const uint32_t sbase = smem_u32(smem);

    const int tid  = threadIdx.x;
    const int wid  = tid >> 5;
    const int lane = tid & 31;
    const int wm   = wid >> 2;         // 0..1
    const int wn   = wid & 3;          // 0..3

    const int n0 = blockIdx.x * BN;    // 0..1535 (rows of packed g_wh)
    const int m0 = blockIdx.y * BM;    // 0..8191

    // loader mapping: thread t -> row t>>1 (0..127), 8-elem half (t&1)
    const int lrow = tid >> 1;
    const int half = tid & 1;
    const __nv_bfloat16* aH = g_xh + (size_t)(m0 + lrow) * 512 + half * 8;
    const __nv_bfloat16* aL = g_xl + (size_t)(m0 + lrow) * 512 + half * 8;
    const __nv_bfloat16* bH = g_wh + (size_t)(n0 + lrow) * 512 + half * 8;
    const __nv_bfloat16* bL = g_wl + (size_t)(n0 + lrow) * 512 + half * 8;
    const uint32_t dst_off = SW32((uint32_t)(lrow * 32 + half * 16));

    // ldmatrix per-lane swizzled offsets (within a region)
    uint32_t a_sw[4], b_sw[4];
    {
        const int r  = wm * 64 + (lane & 15);
        const int kh = (lane >> 4) * 16;
#pragma unroll
        for (int mt = 0; mt < 4; mt++)
            a_sw[mt] = SW32((uint32_t)((r + mt * 16) * 32 + kh));
        const int rb  = wn * 32 + (lane & 7);
        const int khb = ((lane >> 3) & 1) * 16;
#pragma unroll
        for (int nt = 0; nt < 4; nt++)
            b_sw[nt] = SW32((uint32_t)((rb + nt * 8) * 32 + khb));
    }

    float acc[4][4][4];
#pragma unroll
    for (int i = 0; i < 4; i++)
#pragma unroll
        for (int j = 0; j < 4; j++)
#pragma unroll
            for (int r = 0; r < 4; r++) acc[i][j][r] = 0.f;

    // prologue: chunks 0 and 1 in flight
#pragma unroll
    for (int p = 0; p < 2; p++) {
        const uint32_t d = sbase + p * BUFB + dst_off;
        const int kc = p * GKC;
        cpa16(d + R_AHI, aH + kc);
        cpa16(d + R_ALO, aL + kc);
        cpa16(d + R_BHI, bH + kc);
        cpa16(d + R_BLO, bL + kc);
        asm volatile("cp.async.commit_group;");
    }

#pragma unroll 1
    for (int c = 0; c < GNCH; c++) {
        asm volatile("cp.async.wait_group 1;");   // chunk c arrived (this thread)
        __syncthreads();                           // ... for every thread

        const uint32_t bb = sbase + (c & 1) * BUFB;
        uint32_t ah[4][4], al[4][4], bh[4][2], bl[4][2];
#pragma unroll
        for (int mt = 0; mt < 4; mt++) {
            ldsm_x4(bb + R_AHI + a_sw[mt], ah[mt][0], ah[mt][1], ah[mt][2], ah[mt][3]);
            ldsm_x4(bb + R_ALO + a_sw[mt], al[mt][0], al[mt][1], al[mt][2], al[mt][3]);
        }
#pragma unroll
        for (int nt = 0; nt < 4; nt++) {
            ldsm_x2(bb + R_BHI + b_sw[nt], bh[nt][0], bh[nt][1]);
            ldsm_x2(bb + R_BLO + b_sw[nt], bl[nt][0], bl[nt][1]);
        }
#pragma unroll
        for (int mt = 0; mt < 4; mt++)
#pragma unroll
            for (int nt = 0; nt < 4; nt++) {
                mma_bf16(acc[mt][nt], ah[mt], bh[nt]);   // hi*hi
                mma_bf16(acc[mt][nt], ah[mt], bl[nt]);   // hi*lo
                mma_bf16(acc[mt][nt], al[mt], bh[nt]);   // lo*hi
            }

        __syncthreads();                           // all reads of this buffer done
        const int nc = c + 2;
        if (nc < GNCH) {
            const uint32_t d = sbase + (nc & 1) * BUFB + dst_off;
            const int kc = nc * GKC;
            cpa16(d + R_AHI, aH + kc);
            cpa16(d + R_ALO, aL + kc);
            cpa16(d + R_BHI, bH + kc);
            cpa16(d + R_BLO, bL + kc);
        }
        asm volatile("cp.async.commit_group;");    // (possibly empty) keeps counts aligned
    }

    // epilogue: acc -> g_qkv. c0,c1 -> (row qr, cols 2qc,2qc+1); c2,c3 -> row qr+8
    {
        const int qr = lane >> 2, qc = lane & 3;
#pragma unroll
        for (int mt = 0; mt < 4; mt++) {
            const int row = m0 + wm * 64 + mt * 16 + qr;
            float* o0 = g_qkv + (size_t)row * NSTRIDE + n0 + wn * 32;
            float* o1 = g_qkv + (size_t)(row + 8) * NSTRIDE + n0 + wn * 32;
#pragma unroll
            for (int nt = 0; nt < 4; nt++) {
                const int col = nt * 8 + 2 * qc;
                *(float2*)(o0 + col) = make_float2(acc[mt][nt][0], acc[mt][nt][1]);
                *(float2*)(o1 + col) = make_float2(acc[mt][nt][2], acc[mt][nt][3]);
            }
        }
    }
}

// ---------------------------------------------------------------------------
// Exact KNN (top-32 smallest squared dists, self excluded). Warp per query.
// ---------------------------------------------------------------------------
__global__ void __launch_bounds__(128)
knn_kernel(const float* __restrict__ coords)
{
    __shared__ float sd[4 * 32 * 65];
    const unsigned FULL = 0xffffffffu;
    const int warp = threadIdx.x >> 5, lane = threadIdx.x & 31;
    const int g = blockIdx.x * 4 + warp;
    const int b = g >> 11, q = g & 2047;
    const float* cb = coords + (size_t)b * SEQ * 3;
    const float qx = cb[q * 3 + 0], qy = cb[q * 3 + 1], qz = cb[q * 3 + 2];
    float* sw = sd + warp * 2080;
    const float FINF = CUDART_INF_F;

    float best = FINF; int bestc = 0;
    float* srow = sw + lane * 65;
#pragma unroll 4
    for (int i = 0; i < 64; i++) {
        const int c = i * 32 + lane;
        const float dx = cb[c * 3 + 0] - qx;
        const float dy = cb[c * 3 + 1] - qy;
        const float dz = cb[c * 3 + 2] - qz;
        float d = dx * dx + dy * dy + dz * dz;
        if (c == q) d = FINF;
        srow[i] = d;
        if (d < best) { best = d; bestc = c; }
    }
    __syncwarp();

    int myNN = 0;
    for (int r = 0; r < KNN; r++) {
        float v = best; int c = bestc;
#pragma unroll
        for (int off = 16; off; off >>= 1) {
            float v2 = __shfl_xor_sync(FULL, v, off);
            int   c2 = __shfl_xor_sync(FULL, c, off);
            if (v2 < v || (v2 == v && c2 < c)) { v = v2; c = c2; }
        }
        if (lane == r) myNN = c;

        const int L = c & 31, iW = c >> 5;
        float* rrow = sw + L * 65;
        if (lane == (iW & 31)) rrow[iW] = FINF;
        __syncwarp();

        float a0 = rrow[lane];
        float a1 = rrow[lane + 32];
        float nv; int ni;
        if (a0 <= a1) { nv = a0; ni = lane; } else { nv = a1; ni = lane + 32; }
#pragma unroll
        for (int off = 16; off; off >>= 1) {
            float v2 = __shfl_xor_sync(FULL, nv, off);
            int   i2 = __shfl_xor_sync(FULL, ni, off);
            if (v2 < nv || (v2 == nv && i2 < ni)) { nv = v2; ni = i2; }
        }
        if (lane == L) { best = nv; bestc = ni * 32 + L; }
    }
    g_nn[g * KNN + lane] = myNN;
}

// ---------------------------------------------------------------------------
// Sparse attention: block per query (256 thr = 8 warps = 8 heads).
// ---------------------------------------------------------------------------
__global__ void __launch_bounds__(256)
attn_kernel(float* __restrict__ out)
{
    __shared__ __align__(16) float qs[512];
    __shared__ int nns[KNN];
    const unsigned FULL = 0xffffffffu;
    const int g = blockIdx.x;
    const int b = g >> 11;
    const int tid = threadIdx.x;
    const int h = tid >> 5, lane = tid & 31;

    const float* qrow = g_qkv + (size_t)g * NSTRIDE;
    qs[tid]       = qrow[tid];
    qs[tid + 256] = qrow[tid + 256];
    if (tid < KNN) nns[tid] = g_nn[g * KNN + tid];
    __syncthreads();

    const int base_tok = b << 11;

    const int cme = nns[lane];
    const float4* k4 = (const float4*)(g_qkv + (size_t)(base_tok + cme) * NSTRIDE + 512 + h * 64);
    const float4* q4 = (const float4*)(qs + h * 64);
    float s = 0.f;
#pragma unroll
    for (int i = 0; i < 16; i++) {
        float4 kv = k4[i], qv = q4[i];
        s += kv.x * qv.x; s += kv.y * qv.y; s += kv.z * qv.z; s += kv.w * qv.w;
    }
    s *= 0.125f;

    float m = s;
#pragma unroll
    for (int off = 16; off; off >>= 1) m = fmaxf(m, __shfl_xor_sync(FULL, m, off));
    const float e = expf(s - m);
    float sum = e;
#pragma unroll
    for (int off = 16; off; off >>= 1) sum += __shfl_xor_sync(FULL, sum, off);
    const float w = e / sum;

    float acc0 = 0.f, acc1 = 0.f;
#pragma unroll 4
    for (int j = 0; j < KNN; j++) {
        const float wj = __shfl_sync(FULL, w, j);
        const int cj = nns[j];
        const float* vrow = g_qkv + (size_t)(base_tok + cj) * NSTRIDE + 1024 + h * 64;
        acc0 = fmaf(wj, vrow[lane],      acc0);
        acc1 = fmaf(wj, vrow[lane + 32], acc1);
    }
    float* orow = out + (size_t)g * 512 + h * 64;
    orow[lane]      = acc0;
    orow[lane + 32] = acc1;
}

// ---------------------------------------------------------------------------
// metric v3: stage 1 — 512 blocks of partials (fills all SMs), stage 2 — reduce.
// metric[b,h,d] = mean_s K[b,s,h*64+d]; deterministic hierarchical sums.
// ---------------------------------------------------------------------------
__global__ void __launch_bounds__(256)
metric_part(void)
{
    __shared__ float sp[256];
    const int b = blockIdx.x, fb = blockIdx.y, slab = blockIdx.z;
    const int f = threadIdx.x & 31, sl = threadIdx.x >> 5;   // 8 slices x 32 rows
    const float* base = g_qkv + (size_t)b * SEQ * NSTRIDE + 512 + fb * 32 + f
                      + (size_t)(slab * 256 + sl * 32) * NSTRIDE;
    float s = 0.f;
#pragma unroll 4
    for (int i = 0; i < 32; i++) s += base[(size_t)i * NSTRIDE];
    sp[sl * 32 + f] = s;
    __syncthreads();
#pragma unroll
    for (int st = 4; st >= 1; st >>= 1) {
        if (sl < st) sp[sl * 32 + f] += sp[(sl + st) * 32 + f];
        __syncthreads();
    }
    if (sl == 0) g_mpart[((b * 16 + fb) * 8 + slab) * 32 + f] = sp[f];
}

__global__ void __launch_bounds__(32)
metric_fin(float* __restrict__ out)
{
    const int b = blockIdx.x, fb = blockIdx.y, f = threadIdx.x;
    const float* p = g_mpart + ((b * 16 + fb) * 8) * 32 + f;
    float s = 0.f;
#pragma unroll
    for (int slab = 0; slab < 8; slab++) s += p[slab * 32];
    out[(size_t)NQ * FDIM + (size_t)b * 512 + fb * 32 + f] = s * (1.0f / 2048.0f);
}

// ---------------------------------------------------------------------------
extern "C" void kernel_launch(void* const* d_in, const int* in_sizes, int n_in,
                              void* d_out, int out_size)
{
    const float* x      = (const float*)d_in[0];
    const float* coords = (const float*)d_in[1];
    const float* Wq     = (const float*)d_in[2];
    const float* Wk     = (const float*)d_in[3];
    const float* Wv     = (const float*)d_in[4];
    float* out = (float*)d_out;

    knn_kernel<<<2048, 128>>>(coords);                         // coords only
    split_kernel<<<(XN8 + WN8 + 255) / 256, 256>>>(x, Wq, Wk, Wv);
    gemm_mma_kernel<<<dim3(12, 64), 256>>>();                  // reads g_xh/g_xl/g_wh/g_wl
    attn_kernel<<<8192, 256>>>(out);                           // needs g_qkv + g_nn
    metric_part<<<dim3(4, 16, 8), 256>>>();                    // needs g_qkv (K part)
    metric_fin<<<dim3(4, 16), 32>>>(out);
}

// round 11
// speedup vs baseline: 1.6284x; 1.6284x over previous
#include <cuda_runtime.h>
#include <cuda_bf16.h>
#include <math_constants.h>
#include <cstdint>

// Problem constants
#define SEQ     2048
#define NBATCH  4
#define FDIM    512
#define NQ      8192      // NBATCH * SEQ
#define NSTRIDE 1536      // q|k|v packed per token row
#define KNN     32

// GEMM tiling (single 32KB static-shared buffer)
#define BM 128
#define BN 128
#define SKC 32            // K elems per staged chunk
#define NCH 16            // 512 / 32

// smem byte offsets inside the single buffer; rows are 64B (32 bf16), SW64
#define OFF_AHI 0
#define OFF_ALO (8*1024)
#define OFF_BHI (16*1024)
#define OFF_BLO (24*1024)

// Scratch (no allocations allowed)
__device__ __align__(128) float g_qkv[(size_t)NQ * NSTRIDE];   // ~50 MB
__device__ __align__(128) int   g_nn[NQ * KNN];                // 1 MB
__device__ __align__(128) float g_mpart[4 * 16 * 8 * 32];      // 64 KB

// ---------------------------------------------------------------------------
__device__ __forceinline__ uint32_t smem_u32(const void* p) {
    uint32_t a;
    asm("{ .reg .u64 t; cvta.to.shared.u64 t, %1; cvt.u32.u64 %0, t; }" : "=r"(a) : "l"(p));
    return a;
}
#define SW64(off) ((off) ^ (((off) >> 3) & 0x30))

// Split fp32 into hi/lo bf16 (x == hi + lo + O(2^-18 x))
__device__ __forceinline__ void split_bf16(float x, uint32_t& h, uint32_t& l) {
    __nv_bfloat16 bh = __float2bfloat16_rn(x);
    float r = x - __bfloat162float(bh);           // exact in fp32
    __nv_bfloat16 bl = __float2bfloat16_rn(r);
    h = (uint32_t)__bfloat16_as_ushort(bh);
    l = (uint32_t)__bfloat16_as_ushort(bl);
}

// Pack 8 fp32 -> 16B hi-bf16 + 16B lo-bf16
__device__ __forceinline__ void pack8(const float4& f0, const float4& f1,
                                      uint4& hi, uint4& lo) {
    uint32_t h0,l0,h1,l1,h2,l2,h3,l3,h4,l4,h5,l5,h6,l6,h7,l7;
    split_bf16(f0.x,h0,l0); split_bf16(f0.y,h1,l1);
    split_bf16(f0.z,h2,l2); split_bf16(f0.w,h3,l3);
    split_bf16(f1.x,h4,l4); split_bf16(f1.y,h5,l5);
    split_bf16(f1.z,h6,l6); split_bf16(f1.w,h7,l7);
    hi.x = h0 | (h1<<16); hi.y = h2 | (h3<<16); hi.z = h4 | (h5<<16); hi.w = h6 | (h7<<16);
    lo.x = l0 | (l1<<16); lo.y = l2 | (l3<<16); lo.z = l4 | (l5<<16); lo.w = l6 | (l7<<16);
}

__device__ __forceinline__ void ldsm_x4(uint32_t a, uint32_t& r0, uint32_t& r1,
                                        uint32_t& r2, uint32_t& r3) {
    asm volatile("ldmatrix.sync.aligned.m8n8.x4.shared.b16 {%0,%1,%2,%3}, [%4];"
                 : "=r"(r0), "=r"(r1), "=r"(r2), "=r"(r3) : "r"(a));
}
__device__ __forceinline__ void ldsm_x2(uint32_t a, uint32_t& r0, uint32_t& r1) {
    asm volatile("ldmatrix.sync.aligned.m8n8.x2.shared.b16 {%0,%1}, [%2];"
                 : "=r"(r0), "=r"(r1) : "r"(a));
}
__device__ __forceinline__ void mma_bf16(float* d, const uint32_t* a, const uint32_t* b) {
    asm volatile("mma.sync.aligned.m16n8k16.row.col.f32.bf16.bf16.f32 "
                 "{%0,%1,%2,%3}, {%4,%5,%6,%7}, {%8,%9}, {%0,%1,%2,%3};"
                 : "+f"(d[0]), "+f"(d[1]), "+f"(d[2]), "+f"(d[3])
                 : "r"(a[0]), "r"(a[1]), "r"(a[2]), "r"(a[3]), "r"(b[0]), "r"(b[1]));
}

// ---------------------------------------------------------------------------
// QKV GEMM (round-8 proven version): C[m,n] = sum_k x[m,k] * W[n,k], fp32 via
// bf16 3-term split on mma.sync. CTA 128x128, 8 warps 2(M)x4(N), warp tile
// 64x32. KC=32, single 32KB static buffer, register prefetch hides LDG.
// ---------------------------------------------------------------------------
__global__ void __launch_bounds__(256, 1)
gemm_mma_kernel(const float* __restrict__ A,
                const float* __restrict__ Wq,
                const float* __restrict__ Wk,
                const float* __restrict__ Wv)
{
    __shared__ __align__(1024) char smem[32 * 1024];
    const uint32_t sbase = smem_u32(smem);

    const int tid  = threadIdx.x;
    const int wid  = tid >> 5;
    const int lane = tid & 31;
    const int wm   = wid >> 2;         // 0..1  (M position)
    const int wn   = wid & 3;          // 0..3  (N position)

    const int n0 = blockIdx.x * BN;    // 0..1535
    const int m0 = blockIdx.y * BM;    // 0..8191
    const float* Bmat = (n0 < 512) ? Wq : (n0 < 1024) ? Wk : Wv;
    const int nloc = n0 & 511;

    const int lrow  = tid >> 1;
    const int lcol  = (tid & 1) * 16;             // fp32 elems within chunk
    const float* Ap = A    + (size_t)(m0   + lrow) * 512 + lcol;
    const float* Bp = Bmat + (size_t)(nloc + lrow) * 512 + lcol;

    uint32_t st_off[2];
#pragma unroll
    for (int g = 0; g < 2; g++)
        st_off[g] = SW64((uint32_t)(lrow * 64 + lcol * 2 + g * 16));

    uint32_t a_off[4];
    {
        const int r  = wm * 64 + (lane & 15);
        const int kh = (lane >> 4) * 16;
#pragma unroll
        for (int mt = 0; mt < 4; mt++)
            a_off[mt] = (uint32_t)((r + mt * 16) * 64 + kh);
    }
    uint32_t b_off[4];
    {
        const int r  = wn * 32 + (lane & 7);
        const int kh = ((lane >> 3) & 1) * 16;
#pragma unroll
        for (int nt = 0; nt < 4; nt++)
            b_off[nt] = (uint32_t)((r + nt * 8) * 64 + kh);
    }

    float acc[4][4][4];
#pragma unroll
    for (int i = 0; i < 4; i++)
#pragma unroll
        for (int j = 0; j < 4; j++)
#pragma unroll
            for (int r = 0; r < 4; r++) acc[i][j][r] = 0.f;

    float4 ra0, ra1, ra2, ra3, rb0, rb1, rb2, rb3;

    ra0 = *(const float4*)(Ap + 0);  ra1 = *(const float4*)(Ap + 4);
    ra2 = *(const float4*)(Ap + 8);  ra3 = *(const float4*)(Ap + 12);
    rb0 = *(const float4*)(Bp + 0);  rb1 = *(const float4*)(Bp + 4);
    rb2 = *(const float4*)(Bp + 8);  rb3 = *(const float4*)(Bp + 12);
    {
        uint4 hi, lo;
        pack8(ra0, ra1, hi, lo);
        *(uint4*)(smem + OFF_AHI + st_off[0]) = hi;
        *(uint4*)(smem + OFF_ALO + st_off[0]) = lo;
        pack8(ra2, ra3, hi, lo);
        *(uint4*)(smem + OFF_AHI + st_off[1]) = hi;
        *(uint4*)(smem + OFF_ALO + st_off[1]) = lo;
        pack8(rb0, rb1, hi, lo);
        *(uint4*)(smem + OFF_BHI + st_off[0]) = hi;
        *(uint4*)(smem + OFF_BLO + st_off[0]) = lo;
        pack8(rb2, rb3, hi, lo);
        *(uint4*)(smem + OFF_BHI + st_off[1]) = hi;
        *(uint4*)(smem + OFF_BLO + st_off[1]) = lo;
    }
    __syncthreads();

#pragma unroll 1
    for (int c = 0; c < NCH; c++) {
        if (c < NCH - 1) {
            const int kc = (c + 1) * SKC;
            ra0 = *(const float4*)(Ap + kc + 0);  ra1 = *(const float4*)(Ap + kc + 4);
            ra2 = *(const float4*)(Ap + kc + 8);  ra3 = *(const float4*)(Ap + kc + 12);
            rb0 = *(const float4*)(Bp + kc + 0);  rb1 = *(const float4*)(Bp + kc + 4);
            rb2 = *(const float4*)(Bp + kc + 8);  rb3 = *(const float4*)(Bp + kc + 12);
        }

#pragma unroll
        for (int ks = 0; ks < 2; ks++) {
            const uint32_t kso = (uint32_t)(ks * 32);
            uint32_t ah[4][4], al[4][4], bh[4][2], bl[4][2];
#pragma unroll
            for (int mt = 0; mt < 4; mt++) {
                const uint32_t o = SW64(a_off[mt] + kso);
                ldsm_x4(sbase + OFF_AHI + o, ah[mt][0], ah[mt][1], ah[mt][2], ah[mt][3]);
                ldsm_x4(sbase + OFF_ALO + o, al[mt][0], al[mt][1], al[mt][2], al[mt][3]);
            }
#pragma unroll
            for (int nt = 0; nt < 4; nt++) {
                const uint32_t o = SW64(b_off[nt] + kso);
                ldsm_x2(sbase + OFF_BHI + o, bh[nt][0], bh[nt][1]);
                ldsm_x2(sbase + OFF_BLO + o, bl[nt][0], bl[nt][1]);
            }
#pragma unroll
            for (int mt = 0; mt < 4; mt++)
#pragma unroll
                for (int nt = 0; nt < 4; nt++) {
                    mma_bf16(acc[mt][nt], ah[mt], bh[nt]);   // hi*hi
                    mma_bf16(acc[mt][nt], ah[mt], bl[nt]);   // hi*lo
                    mma_bf16(acc[mt][nt], al[mt], bh[nt]);   // lo*hi
                }
        }

        if (c < NCH - 1) {
            __syncthreads();
            uint4 hi, lo;
            pack8(ra0, ra1, hi, lo);
            *(uint4*)(smem + OFF_AHI + st_off[0]) = hi;
            *(uint4*)(smem + OFF_ALO + st_off[0]) = lo;
            pack8(ra2, ra3, hi, lo);
            *(uint4*)(smem + OFF_AHI + st_off[1]) = hi;
            *(uint4*)(smem + OFF_ALO + st_off[1]) = lo;
            pack8(rb0, rb1, hi, lo);
            *(uint4*)(smem + OFF_BHI + st_off[0]) = hi;
            *(uint4*)(smem + OFF_BLO + st_off[0]) = lo;
            pack8(rb2, rb3, hi, lo);
            *(uint4*)(smem + OFF_BHI + st_off[1]) = hi;
            *(uint4*)(smem + OFF_BLO + st_off[1]) = lo;
            __syncthreads();
        }
    }

    {
        const int qr = lane >> 2, qc = lane & 3;
#pragma unroll
        for (int mt = 0; mt < 4; mt++) {
            const int row = m0 + wm * 64 + mt * 16 + qr;
            float* o0 = g_qkv + (size_t)row * NSTRIDE + n0 + wn * 32;
            float* o1 = g_qkv + (size_t)(row + 8) * NSTRIDE + n0 + wn * 32;
#pragma unroll
            for (int nt = 0; nt < 4; nt++) {
                const int col = nt * 8 + 2 * qc;
                *(float2*)(o0 + col) = make_float2(acc[mt][nt][0], acc[mt][nt][1]);
                *(float2*)(o1 + col) = make_float2(acc[mt][nt][2], acc[mt][nt][3]);
            }
        }
    }
}

// ---------------------------------------------------------------------------
// Exact KNN (top-32 smallest squared dists, self excluded). Warp per query.
// ---------------------------------------------------------------------------
__global__ void __launch_bounds__(128)
knn_kernel(const float* __restrict__ coords)
{
    __shared__ float sd[4 * 32 * 65];
    const unsigned FULL = 0xffffffffu;
    const int warp = threadIdx.x >> 5, lane = threadIdx.x & 31;
    const int g = blockIdx.x * 4 + warp;
    const int b = g >> 11, q = g & 2047;
    const float* cb = coords + (size_t)b * SEQ * 3;
    const float qx = cb[q * 3 + 0], qy = cb[q * 3 + 1], qz = cb[q * 3 + 2];
    float* sw = sd + warp * 2080;
    const float FINF = CUDART_INF_F;

    float best = FINF; int bestc = 0;
    float* srow = sw + lane * 65;
#pragma unroll 4
    for (int i = 0; i < 64; i++) {
        const int c = i * 32 + lane;
        const float dx = cb[c * 3 + 0] - qx;
        const float dy = cb[c * 3 + 1] - qy;
        const float dz = cb[c * 3 + 2] - qz;
        float d = dx * dx + dy * dy + dz * dz;
        if (c == q) d = FINF;
        srow[i] = d;
        if (d < best) { best = d; bestc = c; }
    }
    __syncwarp();

    int myNN = 0;
    for (int r = 0; r < KNN; r++) {
        float v = best; int c = bestc;
#pragma unroll
        for (int off = 16; off; off >>= 1) {
            float v2 = __shfl_xor_sync(FULL, v, off);
            int   c2 = __shfl_xor_sync(FULL, c, off);
            if (v2 < v || (v2 == v && c2 < c)) { v = v2; c = c2; }
        }
        if (lane == r) myNN = c;

        const int L = c & 31, iW = c >> 5;
        float* rrow = sw + L * 65;
        if (lane == (iW & 31)) rrow[iW] = FINF;
        __syncwarp();

        float a0 = rrow[lane];
        float a1 = rrow[lane + 32];
        float nv; int ni;
        if (a0 <= a1) { nv = a0; ni = lane; } else { nv = a1; ni = lane + 32; }
#pragma unroll
        for (int off = 16; off; off >>= 1) {
            float v2 = __shfl_xor_sync(FULL, nv, off);
            int   i2 = __shfl_xor_sync(FULL, ni, off);
            if (v2 < nv || (v2 == nv && i2 < ni)) { nv = v2; ni = i2; }
        }
        if (lane == L) { best = nv; bestc = ni * 32 + L; }
    }
    g_nn[g * KNN + lane] = myNN;
}

// ---------------------------------------------------------------------------
// Sparse attention v2: block per query (8 warps = 8 heads), lane = dimension.
// Score phase transposed for COALESCED K loads: for each neighbor j, every
// lane loads k[lane] / k[lane+32] (2 wavefronts vs 64), 2-elem partial, and a
// 5-level shfl tree yields s_j (independent chains pipeline across the
// unrolled j loop). q lives in 2 registers per lane; no q smem tile.
// ---------------------------------------------------------------------------
__global__ void __launch_bounds__(256)
attn_kernel(float* __restrict__ out)
{
    __shared__ int nns[KNN];
    const unsigned FULL = 0xffffffffu;
    const int g = blockIdx.x;
    const int b = g >> 11;
    const int tid = threadIdx.x;
    const int h = tid >> 5, lane = tid & 31;

    if (tid < KNN) nns[tid] = g_nn[g * KNN + tid];
    const float* qrow = g_qkv + (size_t)g * NSTRIDE + h * 64;
    const float q0 = qrow[lane];
    const float q1 = qrow[lane + 32];
    __syncthreads();

    const int base_tok = b << 11;

    // scores: lane ends holding s_{lane}
    float s = 0.f;
#pragma unroll
    for (int j = 0; j < KNN; j++) {
        const int cj = nns[j];
        const float* krow = g_qkv + (size_t)(base_tok + cj) * NSTRIDE + 512 + h * 64;
        float p = q0 * krow[lane] + q1 * krow[lane + 32];
#pragma unroll
        for (int off = 16; off; off >>= 1) p += __shfl_xor_sync(FULL, p, off);
        if (lane == j) s = p;
    }
    s *= 0.125f;   // 1/sqrt(64)

    // softmax across the 32 neighbors (one per lane)
    float m = s;
#pragma unroll
    for (int off = 16; off; off >>= 1) m = fmaxf(m, __shfl_xor_sync(FULL, m, off));
    const float e = expf(s - m);
    float sum = e;
#pragma unroll
    for (int off = 16; off; off >>= 1) sum += __shfl_xor_sync(FULL, sum, off);
    const float w = e / sum;

    // weighted V accumulation, coalesced per-j
    float acc0 = 0.f, acc1 = 0.f;
#pragma unroll 4
    for (int j = 0; j < KNN; j++) {
        const float wj = __shfl_sync(FULL, w, j);
        const int cj = nns[j];
        const float* vrow = g_qkv + (size_t)(base_tok + cj) * NSTRIDE + 1024 + h * 64;
        acc0 = fmaf(wj, vrow[lane],      acc0);
        acc1 = fmaf(wj, vrow[lane + 32], acc1);
    }
    float* orow = out + (size_t)g * 512 + h * 64;
    orow[lane]      = acc0;
    orow[lane + 32] = acc1;
}

// ---------------------------------------------------------------------------
// metric: stage 1 — 512 partial blocks (fills the chip), stage 2 — reduce.
// metric[b,h,d] = mean_s K[b,s,h*64+d]; deterministic hierarchical sums.
// ---------------------------------------------------------------------------
__global__ void __launch_bounds__(256)
metric_part(void)
{
    __shared__ float sp[256];
    const int b = blockIdx.x, fb = blockIdx.y, slab = blockIdx.z;
    const int f = threadIdx.x & 31, sl = threadIdx.x >> 5;   // 8 slices x 32 rows
    const float* base = g_qkv + (size_t)b * SEQ * NSTRIDE + 512 + fb * 32 + f
                      + (size_t)(slab * 256 + sl * 32) * NSTRIDE;
    float s = 0.f;
#pragma unroll 4
    for (int i = 0; i < 32; i++) s += base[(size_t)i * NSTRIDE];
    sp[sl * 32 + f] = s;
    __syncthreads();
#pragma unroll
    for (int st = 4; st >= 1; st >>= 1) {
        if (sl < st) sp[sl * 32 + f] += sp[(sl + st) * 32 + f];
        __syncthreads();
    }
    if (sl == 0) g_mpart[((b * 16 + fb) * 8 + slab) * 32 + f] = sp[f];
}

__global__ void __launch_bounds__(32)
metric_fin(float* __restrict__ out)
{
    const int b = blockIdx.x, fb = blockIdx.y, f = threadIdx.x;
    const float* p = g_mpart + ((b * 16 + fb) * 8) * 32 + f;
    float s = 0.f;
#pragma unroll
    for (int slab = 0; slab < 8; slab++) s += p[slab * 32];
    out[(size_t)NQ * FDIM + (size_t)b * 512 + fb * 32 + f] = s * (1.0f / 2048.0f);
}

// ---------------------------------------------------------------------------
extern "C" void kernel_launch(void* const* d_in, const int* in_sizes, int n_in,
                              void* d_out, int out_size)
{
    const float* x      = (const float*)d_in[0];
    const float* coords = (const float*)d_in[1];
    const float* Wq     = (const float*)d_in[2];
    const float* Wk     = (const float*)d_in[3];
    const float* Wv     = (const float*)d_in[4];
    float* out = (float*)d_out;

    knn_kernel<<<2048, 128>>>(coords);                    // coords only
    gemm_mma_kernel<<<dim3(12, 64), 256>>>(x, Wq, Wk, Wv);
    attn_kernel<<<8192, 256>>>(out);                      // needs g_qkv + g_nn
    metric_part<<<dim3(4, 16, 8), 256>>>();               // needs g_qkv (K part)
    metric_fin<<<dim3(4, 16), 32>>>(out);
}

// round 12
// speedup vs baseline: 1.8701x; 1.1485x over previous
#include <cuda_runtime.h>
#include <cuda_bf16.h>
#include <math_constants.h>
#include <cstdint>

// Problem constants
#define SEQ     2048
#define NBATCH  4
#define FDIM    512
#define NQ      8192      // NBATCH * SEQ
#define NSTRIDE 1536      // q|k|v packed per token row
#define KNN     32

// GEMM tiling (single 32KB static-shared buffer)
#define BM 128
#define BN 128
#define SKC 32            // K elems per staged chunk
#define NCH 16            // 512 / 32

// smem byte offsets inside the single buffer; rows are 64B (32 bf16), SW64
#define OFF_AHI 0
#define OFF_ALO (8*1024)
#define OFF_BHI (16*1024)
#define OFF_BLO (24*1024)

// Scratch (no allocations allowed)
__device__ __align__(128) float          g_qkv[(size_t)NQ * NSTRIDE];  // ~50 MB
__device__ __align__(128) int            g_nn[NQ * KNN];               // 1 MB
__device__ __align__(128) float          g_mpart[4 * 16 * 8 * 32];     // 64 KB
__device__ __align__(128) __nv_bfloat16  g_xh[(size_t)NQ * FDIM];      // 8 MB
__device__ __align__(128) __nv_bfloat16  g_xl[(size_t)NQ * FDIM];      // 8 MB
__device__ __align__(128) __nv_bfloat16  g_wh[1536 * 512];             // 1.5 MB
__device__ __align__(128) __nv_bfloat16  g_wl[1536 * 512];             // 1.5 MB

// ---------------------------------------------------------------------------
__device__ __forceinline__ uint32_t smem_u32(const void* p) {
    uint32_t a;
    asm("{ .reg .u64 t; cvta.to.shared.u64 t, %1; cvt.u32.u64 %0, t; }" : "=r"(a) : "l"(p));
    return a;
}
#define SW64(off) ((off) ^ (((off) >> 3) & 0x30))

// Split fp32 into hi/lo bf16 (x == hi + lo + O(2^-18 x))
__device__ __forceinline__ void split_bf16(float x, uint32_t& h, uint32_t& l) {
    __nv_bfloat16 bh = __float2bfloat16_rn(x);
    float r = x - __bfloat162float(bh);           // exact in fp32
    __nv_bfloat16 bl = __float2bfloat16_rn(r);
    h = (uint32_t)__bfloat16_as_ushort(bh);
    l = (uint32_t)__bfloat16_as_ushort(bl);
}
__device__ __forceinline__ void pack8(const float4& f0, const float4& f1,
                                      uint4& hi, uint4& lo) {
    uint32_t h0,l0,h1,l1,h2,l2,h3,l3,h4,l4,h5,l5,h6,l6,h7,l7;
    split_bf16(f0.x,h0,l0); split_bf16(f0.y,h1,l1);
    split_bf16(f0.z,h2,l2); split_bf16(f0.w,h3,l3);
    split_bf16(f1.x,h4,l4); split_bf16(f1.y,h5,l5);
    split_bf16(f1.z,h6,l6); split_bf16(f1.w,h7,l7);
    hi.x = h0 | (h1<<16); hi.y = h2 | (h3<<16); hi.z = h4 | (h5<<16); hi.w = h6 | (h7<<16);
    lo.x = l0 | (l1<<16); lo.y = l2 | (l3<<16); lo.z = l4 | (l5<<16); lo.w = l6 | (l7<<16);
}

__device__ __forceinline__ void ldsm_x4(uint32_t a, uint32_t& r0, uint32_t& r1,
                                        uint32_t& r2, uint32_t& r3) {
    asm volatile("ldmatrix.sync.aligned.m8n8.x4.shared.b16 {%0,%1,%2,%3}, [%4];"
                 : "=r"(r0), "=r"(r1), "=r"(r2), "=r"(r3) : "r"(a));
}
__device__ __forceinline__ void ldsm_x2(uint32_t a, uint32_t& r0, uint32_t& r1) {
    asm volatile("ldmatrix.sync.aligned.m8n8.x2.shared.b16 {%0,%1}, [%2];"
                 : "=r"(r0), "=r"(r1) : "r"(a));
}
__device__ __forceinline__ void mma_bf16(float* d, const uint32_t* a, const uint32_t* b) {
    asm volatile("mma.sync.aligned.m16n8k16.row.col.f32.bf16.bf16.f32 "
                 "{%0,%1,%2,%3}, {%4,%5,%6,%7}, {%8,%9}, {%0,%1,%2,%3};"
                 : "+f"(d[0]), "+f"(d[1]), "+f"(d[2]), "+f"(d[3])
                 : "r"(a[0]), "r"(a[1]), "r"(a[2]), "r"(a[3]), "r"(b[0]), "r"(b[1]));
}

// ---------------------------------------------------------------------------
// Pre-split x and W into bf16 hi/lo copies (one pass, out of the GEMM loop).
// Thread handles 8 contiguous elems. g_wh rows: 0-511 Wq, 512-1023 Wk, 1024+ Wv.
// ---------------------------------------------------------------------------
#define XN8 (NQ * FDIM / 8)        // 524288
#define WN8 (1536 * 512 / 8)       // 98304
__global__ void __launch_bounds__(256)
split_kernel(const float* __restrict__ x,
             const float* __restrict__ Wq,
             const float* __restrict__ Wk,
             const float* __restrict__ Wv)
{
    const int idx = blockIdx.x * 256 + threadIdx.x;
    if (idx < XN8) {
        const size_t o = (size_t)idx * 8;
        float4 f0 = *(const float4*)(x + o);
        float4 f1 = *(const float4*)(x + o + 4);
        uint4 hi, lo; pack8(f0, f1, hi, lo);
        *(uint4*)(g_xh + o) = hi;
        *(uint4*)(g_xl + o) = lo;
    } else if (idx < XN8 + WN8) {
        const size_t o = (size_t)(idx - XN8) * 8;
        const int m = (int)(o >> 18);                 // 512*512 elems per matrix
        const size_t li = o & 262143;
        const float* src = (m == 0) ? Wq : (m == 1) ? Wk : Wv;
        float4 f0 = *(const float4*)(src + li);
        float4 f1 = *(const float4*)(src + li + 4);
        uint4 hi, lo; pack8(f0, f1, hi, lo);
        *(uint4*)(g_wh + o) = hi;
        *(uint4*)(g_wl + o) = lo;
    }
}

// ---------------------------------------------------------------------------
// QKV GEMM v4: proven v2 loop skeleton, but operands pre-split -> in-loop
// conversion ALU gone and LDG bytes halved. CTA 128x128, 8 warps 2(M)x4(N),
// warp tile 64x32, KC=32 single 32KB static buffer, register prefetch.
// ---------------------------------------------------------------------------
__global__ void __launch_bounds__(256, 1)
gemm_mma_kernel()
{
    __shared__ __align__(1024) char smem[32 * 1024];
    const uint32_t sbase = smem_u32(smem);

    const int tid  = threadIdx.x;
    const int wid  = tid >> 5;
    const int lane = tid & 31;
    const int wm   = wid >> 2;         // 0..1  (M position)
    const int wn   = wid & 3;          // 0..3  (N position)

    const int n0 = blockIdx.x * BN;    // 0..1535 (packed W rows)
    const int m0 = blockIdx.y * BM;    // 0..8191

    const int lrow  = tid >> 1;
    const int lcol  = (tid & 1) * 16;  // bf16 elems within chunk
    const __nv_bfloat16* aH = g_xh + (size_t)(m0 + lrow) * 512 + lcol;
    const __nv_bfloat16* aL = g_xl + (size_t)(m0 + lrow) * 512 + lcol;
    const __nv_bfloat16* bH = g_wh + (size_t)(n0 + lrow) * 512 + lcol;
    const __nv_bfloat16* bL = g_wl + (size_t)(n0 + lrow) * 512 + lcol;

    uint32_t st_off[2];
#pragma unroll
    for (int g = 0; g < 2; g++)
        st_off[g] = SW64((uint32_t)(lrow * 64 + lcol * 2 + g * 16));

    uint32_t a_off[4];
    {
        const int r  = wm * 64 + (lane & 15);
        const int kh = (lane >> 4) * 16;
#pragma unroll
        for (int mt = 0; mt < 4; mt++)
            a_off[mt] = (uint32_t)((r + mt * 16) * 64 + kh);
    }
    uint32_t b_off[4];
    {
        const int r  = wn * 32 + (lane & 7);
        const int kh = ((lane >> 3) & 1) * 16;
#pragma unroll
        for (int nt = 0; nt < 4; nt++)
            b_off[nt] = (uint32_t)((r + nt * 8) * 64 + kh);
    }

    float acc[4][4][4];
#pragma unroll
    for (int i = 0; i < 4; i++)
#pragma unroll
        for (int j = 0; j < 4; j++)
#pragma unroll
            for (int r = 0; r < 4; r++) acc[i][j][r] = 0.f;

    uint4 rah0, rah1, ral0, ral1, rbh0, rbh1, rbl0, rbl1;

    // prologue: chunk 0
    rah0 = *(const uint4*)(aH);     rah1 = *(const uint4*)(aH + 8);
    ral0 = *(const uint4*)(aL);     ral1 = *(const uint4*)(aL + 8);
    rbh0 = *(const uint4*)(bH);     rbh1 = *(const uint4*)(bH + 8);
    rbl0 = *(const uint4*)(bL);     rbl1 = *(const uint4*)(bL + 8);
    *(uint4*)(smem + OFF_AHI + st_off[0]) = rah0;
    *(uint4*)(smem + OFF_AHI + st_off[1]) = rah1;
    *(uint4*)(smem + OFF_ALO + st_off[0]) = ral0;
    *(uint4*)(smem + OFF_ALO + st_off[1]) = ral1;
    *(uint4*)(smem + OFF_BHI + st_off[0]) = rbh0;
    *(uint4*)(smem + OFF_BHI + st_off[1]) = rbh1;
    *(uint4*)(smem + OFF_BLO + st_off[0]) = rbl0;
    *(uint4*)(smem + OFF_BLO + st_off[1]) = rbl1;
    __syncthreads();

#pragma unroll 1
    for (int c = 0; c < NCH; c++) {
        if (c < NCH - 1) {
            const int kc = (c + 1) * SKC;
            rah0 = *(const uint4*)(aH + kc);     rah1 = *(const uint4*)(aH + kc + 8);
            ral0 = *(const uint4*)(aL + kc);     ral1 = *(const uint4*)(aL + kc + 8);
            rbh0 = *(const uint4*)(bH + kc);     rbh1 = *(const uint4*)(bH + kc + 8);
            rbl0 = *(const uint4*)(bL + kc);     rbl1 = *(const uint4*)(bL + kc + 8);
        }

#pragma unroll
        for (int ks = 0; ks < 2; ks++) {
            const uint32_t kso = (uint32_t)(ks * 32);
            uint32_t ah[4][4], al[4][4], bh[4][2], bl[4][2];
#pragma unroll
            for (int mt = 0; mt < 4; mt++) {
                const uint32_t o = SW64(a_off[mt] + kso);
                ldsm_x4(sbase + OFF_AHI + o, ah[mt][0], ah[mt][1], ah[mt][2], ah[mt][3]);
                ldsm_x4(sbase + OFF_ALO + o, al[mt][0], al[mt][1], al[mt][2], al[mt][3]);
            }
#pragma unroll
            for (int nt = 0; nt < 4; nt++) {
                const uint32_t o = SW64(b_off[nt] + kso);
                ldsm_x2(sbase + OFF_BHI + o, bh[nt][0], bh[nt][1]);
                ldsm_x2(sbase + OFF_BLO + o, bl[nt][0], bl[nt][1]);
            }
#pragma unroll
            for (int mt = 0; mt < 4; mt++)
#pragma unroll
                for (int nt = 0; nt < 4; nt++) {
                    mma_bf16(acc[mt][nt], ah[mt], bh[nt]);   // hi*hi
                    mma_bf16(acc[mt][nt], ah[mt], bl[nt]);   // hi*lo
                    mma_bf16(acc[mt][nt], al[mt], bh[nt]);   // lo*hi
                }
        }

        if (c < NCH - 1) {
            __syncthreads();
            *(uint4*)(smem + OFF_AHI + st_off[0]) = rah0;
            *(uint4*)(smem + OFF_AHI + st_off[1]) = rah1;
            *(uint4*)(smem + OFF_ALO + st_off[0]) = ral0;
            *(uint4*)(smem + OFF_ALO + st_off[1]) = ral1;
            *(uint4*)(smem + OFF_BHI + st_off[0]) = rbh0;
            *(uint4*)(smem + OFF_BHI + st_off[1]) = rbh1;
            *(uint4*)(smem + OFF_BLO + st_off[0]) = rbl0;
            *(uint4*)(smem + OFF_BLO + st_off[1]) = rbl1;
            __syncthreads();
        }
    }

    {
        const int qr = lane >> 2, qc = lane & 3;
#pragma unroll
        for (int mt = 0; mt < 4; mt++) {
            const int row = m0 + wm * 64 + mt * 16 + qr;
            float* o0 = g_qkv + (size_t)row * NSTRIDE + n0 + wn * 32;
            float* o1 = g_qkv + (size_t)(row + 8) * NSTRIDE + n0 + wn * 32;
#pragma unroll
            for (int nt = 0; nt < 4; nt++) {
                const int col = nt * 8 + 2 * qc;
                *(float2*)(o0 + col) = make_float2(acc[mt][nt][0], acc[mt][nt][1]);
                *(float2*)(o1 + col) = make_float2(acc[mt][nt][2], acc[mt][nt][3]);
            }
        }
    }
}

// ---------------------------------------------------------------------------
// Exact KNN (top-32 smallest squared dists, self excluded). Warp per query.
// ---------------------------------------------------------------------------
__global__ void __launch_bounds__(128)
knn_kernel(const float* __restrict__ coords)
{
    __shared__ float sd[4 * 32 * 65];
    const unsigned FULL = 0xffffffffu;
    const int warp = threadIdx.x >> 5, lane = threadIdx.x & 31;
    const int g = blockIdx.x * 4 + warp;
    const int b = g >> 11, q = g & 2047;
    const float* cb = coords + (size_t)b * SEQ * 3;
    const float qx = cb[q * 3 + 0], qy = cb[q * 3 + 1], qz = cb[q * 3 + 2];
    float* sw = sd + warp * 2080;
    const float FINF = CUDART_INF_F;

    float best = FINF; int bestc = 0;
    float* srow = sw + lane * 65;
#pragma unroll 4
    for (int i = 0; i < 64; i++) {
        const int c = i * 32 + lane;
        const float dx = cb[c * 3 + 0] - qx;
        const float dy = cb[c * 3 + 1] - qy;
        const float dz = cb[c * 3 + 2] - qz;
        float d = dx * dx + dy * dy + dz * dz;
        if (c == q) d = FINF;
        srow[i] = d;
        if (d < best) { best = d; bestc = c; }
    }
    __syncwarp();

    int myNN = 0;
    for (int r = 0; r < KNN; r++) {
        float v = best; int c = bestc;
#pragma unroll
        for (int off = 16; off; off >>= 1) {
            float v2 = __shfl_xor_sync(FULL, v, off);
            int   c2 = __shfl_xor_sync(FULL, c, off);
            if (v2 < v || (v2 == v && c2 < c)) { v = v2; c = c2; }
        }
        if (lane == r) myNN = c;

        const int L = c & 31, iW = c >> 5;
        float* rrow = sw + L * 65;
        if (lane == (iW & 31)) rrow[iW] = FINF;
        __syncwarp();

        float a0 = rrow[lane];
        float a1 = rrow[lane + 32];
        float nv; int ni;
        if (a0 <= a1) { nv = a0; ni = lane; } else { nv = a1; ni = lane + 32; }
#pragma unroll
        for (int off = 16; off; off >>= 1) {
            float v2 = __shfl_xor_sync(FULL, nv, off);
            int   i2 = __shfl_xor_sync(FULL, ni, off);
            if (v2 < nv || (v2 == nv && i2 < ni)) { nv = v2; ni = i2; }
        }
        if (lane == L) { best = nv; bestc = ni * 32 + L; }
    }
    g_nn[g * KNN + lane] = myNN;
}

// ---------------------------------------------------------------------------
// Fused attention + metric partials.
// attn blocks [0,8192): warp = head, lane = dim pair (2d,2d+1), float2 loads,
//   neighbor ids in registers broadcast via shfl (no smem, no __syncthreads).
// metric blocks [8192,8704): 32-row K-column partial sums.
// ---------------------------------------------------------------------------
__global__ void __launch_bounds__(256)
attn_metric_kernel(float* __restrict__ out)
{
    const unsigned FULL = 0xffffffffu;
    const int tid = threadIdx.x;

    if (blockIdx.x >= 8192) {   // ---- metric partial role ----
        __shared__ float sp[256];
        const int idx = blockIdx.x - 8192;          // 0..511
        const int b = idx >> 7, fb = (idx >> 3) & 15, slab = idx & 7;
        const int f = tid & 31, sl = tid >> 5;
        const float* base = g_qkv + (size_t)b * SEQ * NSTRIDE + 512 + fb * 32 + f
                          + (size_t)(slab * 256 + sl * 32) * NSTRIDE;
        float s = 0.f;
#pragma unroll 4
        for (int i = 0; i < 32; i++) s += base[(size_t)i * NSTRIDE];
        sp[sl * 32 + f] = s;
        __syncthreads();
#pragma unroll
        for (int st = 4; st >= 1; st >>= 1) {
            if (sl < st) sp[sl * 32 + f] += sp[(sl + st) * 32 + f];
            __syncthreads();
        }
        if (sl == 0) g_mpart[((b * 16 + fb) * 8 + slab) * 32 + f] = sp[f];
        return;
    }

    // ---- attention role ----
    const int g = blockIdx.x;
    const int b = g >> 11;
    const int h = tid >> 5, lane = tid & 31;
    const int base_tok = b << 11;

    const int myN = g_nn[g * KNN + lane];           // coalesced, per-warp copy
    const float2* q2 = (const float2*)(g_qkv + (size_t)g * NSTRIDE + h * 64);
    const float2 qv = q2[lane];

    // scores: lane ends holding s_{lane}
    float s = 0.f;
#pragma unroll
    for (int j = 0; j < KNN; j++) {
        const int cj = __shfl_sync(FULL, myN, j);
        const float2* k2 = (const float2*)(g_qkv + (size_t)(base_tok + cj) * NSTRIDE
                                           + 512 + h * 64);
        const float2 kv = k2[lane];
        float p = qv.x * kv.x + qv.y * kv.y;
#pragma unroll
        for (int off = 16; off; off >>= 1) p += __shfl_xor_sync(FULL, p, off);
        if (lane == j) s = p;
    }
    s *= 0.125f;   // 1/sqrt(64)

    // softmax across the 32 neighbors (one per lane)
    float m = s;
#pragma unroll
    for (int off = 16; off; off >>= 1) m = fmaxf(m, __shfl_xor_sync(FULL, m, off));
    const float e = expf(s - m);
    float sum = e;
#pragma unroll
    for (int off = 16; off; off >>= 1) sum += __shfl_xor_sync(FULL, sum, off);
    const float w = e / sum;

    // weighted V accumulation, coalesced float2 per-j
    float ax = 0.f, ay = 0.f;
#pragma unroll 4
    for (int j = 0; j < KNN; j++) {
        const int cj = __shfl_sync(FULL, myN, j);
        const float wj = __shfl_sync(FULL, w, j);
        const float2* v2 = (const float2*)(g_qkv + (size_t)(base_tok + cj) * NSTRIDE
                                           + 1024 + h * 64);
        const float2 vv = v2[lane];
        ax = fmaf(wj, vv.x, ax);
        ay = fmaf(wj, vv.y, ay);
    }
    ((float2*)(out + (size_t)g * 512 + h * 64))[lane] = make_float2(ax, ay);
}

__global__ void __launch_bounds__(32)
metric_fin(float* __restrict__ out)
{
    const int b = blockIdx.x, fb = blockIdx.y, f = threadIdx.x;
    const float* p = g_mpart + ((b * 16 + fb) * 8) * 32 + f;
    float s = 0.f;
#pragma unroll
    for (int slab = 0; slab < 8; slab++) s += p[slab * 32];
    out[(size_t)NQ * FDIM + (size_t)b * 512 + fb * 32 + f] = s * (1.0f / 2048.0f);
}

// ---------------------------------------------------------------------------
extern "C" void kernel_launch(void* const* d_in, const int* in_sizes, int n_in,
                              void* d_out, int out_size)
{
    const float* x      = (const float*)d_in[0];
    const float* coords = (const float*)d_in[1];
    const float* Wq     = (const float*)d_in[2];
    const float* Wk     = (const float*)d_in[3];
    const float* Wv     = (const float*)d_in[4];
    float* out = (float*)d_out;

    split_kernel<<<(XN8 + WN8 + 255) / 256, 256>>>(x, Wq, Wk, Wv);
    knn_kernel<<<2048, 128>>>(coords);                 // coords only
    gemm_mma_kernel<<<dim3(12, 64), 256>>>();          // reads g_xh/g_xl/g_wh/g_wl
    attn_metric_kernel<<<8704, 256>>>(out);            // needs g_qkv + g_nn
    metric_fin<<<dim3(4, 16), 32>>>(out);
}